// round 7
// baseline (speedup 1.0000x reference)
#include <cuda_runtime.h>

// ypred: [B=8, L=32, J=128, N=512] fp32 -> d_in[0]
// xyz:   [B=8, L=32, N=512, 3]     fp32 -> d_in[1]
// out:   scalar fp32 mean
#define NPTS 512
#define JDIM 128
#define JCHUNK 32
#define NCHUNK 4
#define TSTRIDE 513          // odd stride => conflict-free column reads
#define NBL 256

__device__ double g_partials[NBL];
__device__ unsigned int g_ticket = 0;

// ---- packed f32x2 helpers (sm_100+) ----
__device__ __forceinline__ unsigned long long pack2(float lo, float hi) {
    unsigned long long r;
    asm("mov.b64 %0, {%1, %2};" : "=l"(r) : "f"(lo), "f"(hi));
    return r;
}
__device__ __forceinline__ void unpack2(unsigned long long v, float& lo, float& hi) {
    asm("mov.b64 {%0, %1}, %2;" : "=f"(lo), "=f"(hi) : "l"(v));
}
__device__ __forceinline__ unsigned long long fma2(unsigned long long a, unsigned long long b,
                                                   unsigned long long c) {
    unsigned long long d;
    asm("fma.rn.f32x2 %0, %1, %2, %3;" : "=l"(d) : "l"(a), "l"(b), "l"(c));
    return d;
}

// 3-fma distance: v = fma(z, -2z_m, fma(y, -2y_m, fma(x, -2x_m, sq_m)))
// a = (nx0,nx1 | ny0,ny1), b = (nz0,nz1 | sq0,sq1)  (n* = -2*coord)
__device__ __forceinline__ float2 pairv3(ulonglong2 a, ulonglong2 b,
                                         unsigned long long x2,
                                         unsigned long long y2,
                                         unsigned long long z2) {
    unsigned long long t = fma2(x2, a.x, b.y);
    t = fma2(y2, a.y, t);
    t = fma2(z2, b.x, t);
    float2 r;
    unpack2(t, r.x, r.y);
    return r;
}

__device__ __forceinline__ float max8(const float* v) {
    return fmaxf(fmaxf(fmaxf(v[0], v[1]), fmaxf(v[2], v[3])),
                 fmaxf(fmaxf(v[4], v[5]), fmaxf(v[6], v[7])));
}
__device__ __forceinline__ float min8(const float* v) {
    return fminf(fminf(fminf(v[0], v[1]), fminf(v[2], v[3])),
                 fminf(fminf(v[4], v[5]), fminf(v[6], v[7])));
}
__device__ __forceinline__ float min8m(const float* v, float vself, float INF) {
    float u[8];
    #pragma unroll
    for (int q = 0; q < 8; ++q) u[q] = (v[q] > vself) ? v[q] : INF;
    return min8(u);
}

__device__ __forceinline__ int rescan_max(const ulonglong2* A, const ulonglong2* B,
                                          unsigned long long x2, unsigned long long y2,
                                          unsigned long long z2, int pb, float best) {
    int idx = 2 * pb;
    bool found = false;
    #pragma unroll
    for (int p = 0; p < 4; ++p) {
        float2 v = pairv3(A[pb + p], B[pb + p], x2, y2, z2);
        if (!found && v.x == best) { idx = 2 * (pb + p);     found = true; }
        if (!found && v.y == best) { idx = 2 * (pb + p) + 1; found = true; }
    }
    return idx;
}
__device__ __forceinline__ int rescan_min(const ulonglong2* A, const ulonglong2* B,
                                          unsigned long long x2, unsigned long long y2,
                                          unsigned long long z2, int pb, float best,
                                          bool masked, float vself, float INF) {
    int idx = 2 * pb;
    bool found = false;
    #pragma unroll
    for (int p = 0; p < 4; ++p) {
        float2 v = pairv3(A[pb + p], B[pb + p], x2, y2, z2);
        float u0 = (masked && !(v.x > vself)) ? INF : v.x;
        float u1 = (masked && !(v.y > vself)) ? INF : v.y;
        if (!found && u0 == best) { idx = 2 * (pb + p);     found = true; }
        if (!found && u1 == best) { idx = 2 * (pb + p) + 1; found = true; }
    }
    return idx;
}

// 32 x 4B cp.async: one 32x512 ypred chunk into the stride-513 tile
__device__ __forceinline__ void prefetch_chunk(float* buf, const float* src, int tid) {
    unsigned db = (unsigned)__cvta_generic_to_shared(buf);
    #pragma unroll
    for (int r = 0; r < JCHUNK; ++r) {
        const float* s = src + r * NPTS + tid;
        unsigned d = db + (unsigned)((r * TSTRIDE + tid) * 4);
        asm volatile("cp.async.ca.shared.global [%0], [%1], 4;" :: "r"(d), "l"(s));
    }
    asm volatile("cp.async.commit_group;" ::: "memory");
}

__global__ __launch_bounds__(512, 2)
void cll_fused_kernel(const float* __restrict__ ypred,
                      const float* __restrict__ xyz,
                      float* __restrict__ out) {
    __shared__ float4 pA[NPTS / 2];      // (-2x0,-2x1,-2y0,-2y1) per point pair
    __shared__ float4 pB[NPTS / 2];      // (-2z0,-2z1, sq0, sq1)
    __shared__ int    sidx[NPTS];        // packed (imax | imin<<16) per row
    __shared__ float  mMx[NPTS];         // half-1 publish buffers
    __shared__ int    miMx[NPTS];
    __shared__ float  mMn[NPTS];
    __shared__ int    miMn[NPTS];
    __shared__ double redbuf[256];
    __shared__ int    amLast;
    __shared__ float  tile[JCHUNK * TSTRIDE];

    const int bl  = blockIdx.x;
    const int tid = threadIdx.x;
    const int w   = tid >> 5;
    const int l   = tid & 31;
    const float INF = __int_as_float(0x7f800000);

    const float* yb = ypred + (size_t)bl * (JDIM * NPTS);

    // ---- prefetch ypred chunk 0 under phase 1 ----
    prefetch_chunk(tile, yb, tid);

    // ---- load xyz; store (-2x,-2y,-2z,sq); sq in fixed fma order ----
    {
        const float* xb = xyz + (size_t)bl * NPTS * 3;
        float x = xb[tid * 3 + 0];
        float y = xb[tid * 3 + 1];
        float z = xb[tid * 3 + 2];
        float sq = fmaf(z, z, fmaf(y, y, x * x));
        float* tA = (float*)pA;
        float* tB = (float*)pB;
        int base = (tid >> 1) * 4 + (tid & 1);
        tA[base + 0] = -2.0f * x;     // exact
        tA[base + 2] = -2.0f * y;
        tB[base + 0] = -2.0f * z;
        tB[base + 2] = sq;
    }
    __syncthreads();

    // ---- phase 1: thread (u,h) scans candidate half h for rows u, u+256 ----
    const int u = tid & 255;
    const int h = tid >> 8;                 // warp-uniform
    const int wdiag = u >> 5;               // warp-uniform masked-group window

    const float* tA = (const float*)pA;
    const float* tB = (const float*)pB;
    const ulonglong2* A = (const ulonglong2*)pA;
    const ulonglong2* B = (const ulonglong2*)pB;

    // row 0 = u, row 1 = u + 256 (table base1 = base0 + 512)
    unsigned long long x20, y20, z20, x21, y21, z21;
    float vself0, vself1;
    {
        int b0 = (u >> 1) * 4 + (u & 1);
        float nx0 = tA[b0], ny0 = tA[b0 + 2], nz0 = tB[b0], s0 = tB[b0 + 2];
        float nx1 = tA[b0 + 512], ny1 = tA[b0 + 514];
        float nz1 = tB[b0 + 512], s1 = tB[b0 + 514];
        float x0 = -0.5f * nx0, y0 = -0.5f * ny0, z0 = -0.5f * nz0;   // exact
        float x1 = -0.5f * nx1, y1 = -0.5f * ny1, z1 = -0.5f * nz1;
        x20 = pack2(x0, x0); y20 = pack2(y0, y0); z20 = pack2(z0, z0);
        x21 = pack2(x1, x1); y21 = pack2(y1, y1); z21 = pack2(z1, z1);
        // identical instruction sequence as pairv3 per-lane => diag v == vself
        vself0 = fmaf(z0, nz0, fmaf(y0, ny0, fmaf(x0, nx0, s0)));
        vself1 = fmaf(z1, nz1, fmaf(y1, ny1, fmaf(x1, nx1, s1)));
    }

    float bx0 = -INF, bx1 = -INF, bn0 = INF, bn1 = INF;
    int gx0 = 0, gx1 = 0, gn0 = 0, gn1 = 0;

    #pragma unroll 1
    for (int g = 0; g < 32; ++g) {          // 32 groups x 4 pairs (8 candidates)
        const int pb = (h << 7) + (g << 2);
        ulonglong2 a0 = A[pb + 0], b0 = B[pb + 0];
        ulonglong2 a1 = A[pb + 1], b1 = B[pb + 1];
        ulonglong2 a2 = A[pb + 2], b2 = B[pb + 2];
        ulonglong2 a3 = A[pb + 3], b3 = B[pb + 3];
        const bool win = ((g >> 2) == wdiag);

        // ---- row 0 (sequenced to bound register liveness) ----
        {
            float v[8];
            float2 r;
            r = pairv3(a0, b0, x20, y20, z20); v[0] = r.x; v[1] = r.y;
            r = pairv3(a1, b1, x20, y20, z20); v[2] = r.x; v[3] = r.y;
            r = pairv3(a2, b2, x20, y20, z20); v[4] = r.x; v[5] = r.y;
            r = pairv3(a3, b3, x20, y20, z20); v[6] = r.x; v[7] = r.y;
            float gm = max8(v);
            if (gm > bx0) { bx0 = gm; gx0 = g; }
            float q = (win && h == 0) ? min8m(v, vself0, INF) : min8(v);
            if (q < bn0) { bn0 = q; gn0 = g; }
        }
        // ---- row 1 ----
        {
            float v[8];
            float2 r;
            r = pairv3(a0, b0, x21, y21, z21); v[0] = r.x; v[1] = r.y;
            r = pairv3(a1, b1, x21, y21, z21); v[2] = r.x; v[3] = r.y;
            r = pairv3(a2, b2, x21, y21, z21); v[4] = r.x; v[5] = r.y;
            r = pairv3(a3, b3, x21, y21, z21); v[6] = r.x; v[7] = r.y;
            float gm = max8(v);
            if (gm > bx1) { bx1 = gm; gx1 = g; }
            float q = (win && h == 1) ? min8m(v, vself1, INF) : min8(v);
            if (q < bn1) { bn1 = q; gn1 = g; }
        }
    }

    // ---- O(1) exact first-occurrence epilogue on winning groups ----
    int ix0 = rescan_max(A, B, x20, y20, z20, (h << 7) + (gx0 << 2), bx0);
    int ix1 = rescan_max(A, B, x21, y21, z21, (h << 7) + (gx1 << 2), bx1);
    bool m0 = (h == 0) && ((gn0 >> 2) == wdiag);
    bool m1 = (h == 1) && ((gn1 >> 2) == wdiag);
    int in0 = rescan_min(A, B, x20, y20, z20, (h << 7) + (gn0 << 2), bn0, m0, vself0, INF);
    int in1 = rescan_min(A, B, x21, y21, z21, (h << 7) + (gn1 << 2), bn1, m1, vself1, INF);

    // ---- merge halves (ties keep half 0 = lower candidate indices) ----
    if (h) {
        mMx[u] = bx0;        miMx[u] = ix0;
        mMn[u] = bn0;        miMn[u] = in0;
        mMx[u + 256] = bx1;  miMx[u + 256] = ix1;
        mMn[u + 256] = bn1;  miMn[u + 256] = in1;
    }
    __syncthreads();
    if (!h) {
        if (mMx[u] > bx0) ix0 = miMx[u];
        if (mMn[u] < bn0) in0 = miMn[u];
        sidx[u] = ix0 | (in0 << 16);
        if (mMx[u + 256] > bx1) ix1 = miMx[u + 256];
        if (mMn[u + 256] < bn1) in1 = miMn[u + 256];
        sidx[u + 256] = ix1 | (in1 << 16);
    }

    // ---- phase 2: conflict-free gathered dots (indices via LDS broadcast) ----
    asm volatile("cp.async.wait_group 0;" ::: "memory");
    __syncthreads();   // chunk 0 ready; sidx published; table readers done

    float acc = 0.0f;
    const float* tl = tile + l * TSTRIDE;    // lane l owns j-row l
    const float* ta = tl + (w << 5);         // this warp's target columns
    const int* sw = sidx + (w << 5);

    #pragma unroll 1
    for (int c = 0; c < NCHUNK; ++c) {
        #pragma unroll
        for (int i = 0; i < 32; ++i) {
            int pk = sw[i];                  // broadcast LDS (warp-uniform)
            int mt = pk & 0xffff;
            int nt = ((unsigned)pk) >> 16;
            float a  = ta[i];    // bank (l+32w+i)%32 : conflict-free
            float b  = tl[mt];   // bank (l+mt)%32    : conflict-free
            float cc = tl[nt];   // bank (l+nt)%32    : conflict-free
            acc = fmaf(a, b - cc, acc);
        }
        if (c + 1 < NCHUNK) {
            __syncthreads();     // everyone done reading chunk c
            prefetch_chunk(tile, yb + (size_t)(c + 1) * (JCHUNK * NPTS), tid);
            asm volatile("cp.async.wait_group 0;" ::: "memory");
            __syncthreads();     // chunk c+1 visible
        }
    }

    // ---- deterministic reduction: warp butterfly + fixed-order sums ----
    double d = (double)acc;
    #pragma unroll
    for (int off = 16; off > 0; off >>= 1)
        d += __shfl_xor_sync(0xffffffffu, d, off);
    if (l == 0) redbuf[w] = d;
    __syncthreads();

    if (tid == 0) {
        double s = 0.0;
        #pragma unroll
        for (int i = 0; i < 16; ++i) s += redbuf[i];
        g_partials[bl] = s;
        __threadfence();
        unsigned t = atomicAdd(&g_ticket, 1u);
        amLast = (t == NBL - 1) ? 1 : 0;
    }
    __syncthreads();

    // ---- fused finalize: last block sums partials in fixed order ----
    if (amLast) {
        if (tid < NBL) redbuf[tid] = ((const volatile double*)g_partials)[tid];
        __syncthreads();
        #pragma unroll
        for (int s2 = NBL / 2; s2 > 0; s2 >>= 1) {
            if (tid < s2) redbuf[tid] += redbuf[tid + s2];
            __syncthreads();
        }
        if (tid == 0) {
            out[0] = (float)(redbuf[0] / (double)((size_t)NBL * NPTS));
            g_ticket = 0;   // reset for next graph replay
        }
    }
}

extern "C" void kernel_launch(void* const* d_in, const int* in_sizes, int n_in,
                              void* d_out, int out_size) {
    const float* ypred = (const float*)d_in[0];
    const float* xyz   = (const float*)d_in[1];
    float* out = (float*)d_out;
    cll_fused_kernel<<<NBL, 512>>>(ypred, xyz, out);
}

// round 8
// speedup vs baseline: 1.0052x; 1.0052x over previous
#include <cuda_runtime.h>

// ypred: [B=8, L=32, J=128, N=512] fp32 -> d_in[0]
// xyz:   [B=8, L=32, N=512, 3]     fp32 -> d_in[1]
// out:   scalar fp32 mean
#define NPTS 512
#define JDIM 128
#define JC 16                // j-rows per chunk (double-buffered)
#define NCH 8                // 128 / 16
#define TSTRIDE 513          // odd stride => conflict-free column reads
#define NBL 256

__device__ double g_partials[NBL];
__device__ unsigned int g_ticket = 0;

// ---- packed f32x2 helpers (sm_100+) ----
__device__ __forceinline__ unsigned long long pack2(float lo, float hi) {
    unsigned long long r;
    asm("mov.b64 %0, {%1, %2};" : "=l"(r) : "f"(lo), "f"(hi));
    return r;
}
__device__ __forceinline__ void unpack2(unsigned long long v, float& lo, float& hi) {
    asm("mov.b64 {%0, %1}, %2;" : "=f"(lo), "=f"(hi) : "l"(v));
}
__device__ __forceinline__ unsigned long long mul2(unsigned long long a, unsigned long long b) {
    unsigned long long d;
    asm("mul.rn.f32x2 %0, %1, %2;" : "=l"(d) : "l"(a), "l"(b));
    return d;
}
__device__ __forceinline__ unsigned long long fma2(unsigned long long a, unsigned long long b,
                                                   unsigned long long c) {
    unsigned long long d;
    asm("fma.rn.f32x2 %0, %1, %2, %3;" : "=l"(d) : "l"(a), "l"(b), "l"(c));
    return d;
}

// v-pair for one row against point-pair (a=(x0x1,y0y1), b=(z0z1,sq0sq1))
__device__ __forceinline__ float2 pairv(ulonglong2 a, ulonglong2 b,
                                        unsigned long long x2,
                                        unsigned long long y2,
                                        unsigned long long z2,
                                        unsigned long long c2) {
    unsigned long long dot = mul2(x2, a.x);
    dot = fma2(y2, a.y, dot);
    dot = fma2(z2, b.x, dot);
    unsigned long long val = fma2(dot, c2, b.y);   // v = sq_m - 2*dot
    float2 r;
    unpack2(val, r.x, r.y);
    return r;
}

__device__ __forceinline__ float max8(const float* v) {
    return fmaxf(fmaxf(fmaxf(v[0], v[1]), fmaxf(v[2], v[3])),
                 fmaxf(fmaxf(v[4], v[5]), fmaxf(v[6], v[7])));
}
__device__ __forceinline__ float min8(const float* v) {
    return fminf(fminf(fminf(v[0], v[1]), fminf(v[2], v[3])),
                 fminf(fminf(v[4], v[5]), fminf(v[6], v[7])));
}
__device__ __forceinline__ float min8m(const float* v, float negsq, float INF) {
    float u[8];
    #pragma unroll
    for (int q = 0; q < 8; ++q) u[q] = (v[q] > negsq) ? v[q] : INF;
    return min8(u);
}

__device__ __forceinline__ int rescan_max(const ulonglong2* A, const ulonglong2* B,
                                          unsigned long long x2, unsigned long long y2,
                                          unsigned long long z2, unsigned long long c2,
                                          int pb, float best) {
    int idx = 2 * pb;
    bool found = false;
    #pragma unroll
    for (int p = 0; p < 4; ++p) {
        float2 v = pairv(A[pb + p], B[pb + p], x2, y2, z2, c2);
        if (!found && v.x == best) { idx = 2 * (pb + p);     found = true; }
        if (!found && v.y == best) { idx = 2 * (pb + p) + 1; found = true; }
    }
    return idx;
}
__device__ __forceinline__ int rescan_min(const ulonglong2* A, const ulonglong2* B,
                                          unsigned long long x2, unsigned long long y2,
                                          unsigned long long z2, unsigned long long c2,
                                          int pb, float best, bool masked, float negsq,
                                          float INF) {
    int idx = 2 * pb;
    bool found = false;
    #pragma unroll
    for (int p = 0; p < 4; ++p) {
        float2 v = pairv(A[pb + p], B[pb + p], x2, y2, z2, c2);
        float u0 = (masked && !(v.x > negsq)) ? INF : v.x;
        float u1 = (masked && !(v.y > negsq)) ? INF : v.y;
        if (!found && u0 == best) { idx = 2 * (pb + p);     found = true; }
        if (!found && u1 == best) { idx = 2 * (pb + p) + 1; found = true; }
    }
    return idx;
}

// 16 x 4B cp.async: one 16x512 ypred chunk into a stride-513 tile buffer
__device__ __forceinline__ void prefetch_chunk16(float* buf, const float* src, int tid) {
    unsigned db = (unsigned)__cvta_generic_to_shared(buf);
    #pragma unroll
    for (int r = 0; r < JC; ++r) {
        const float* s = src + r * NPTS + tid;
        unsigned d = db + (unsigned)((r * TSTRIDE + tid) * 4);
        asm volatile("cp.async.ca.shared.global [%0], [%1], 4;" :: "r"(d), "l"(s));
    }
    asm volatile("cp.async.commit_group;" ::: "memory");
}

__global__ __launch_bounds__(512, 2)
void cll_fused_kernel(const float* __restrict__ ypred,
                      const float* __restrict__ xyz,
                      float* __restrict__ out) {
    __shared__ float4 pA[NPTS / 2];      // (x0,x1,y0,y1) per point pair
    __shared__ float4 pB[NPTS / 2];      // (z0,z1,sq0,sq1)
    __shared__ int    sidx[NPTS];        // packed (imax | imin<<16) per row
    __shared__ float  mMx[NPTS];         // half-1 publish buffers
    __shared__ int    miMx[NPTS];
    __shared__ float  mMn[NPTS];
    __shared__ int    miMn[NPTS];
    __shared__ double redbuf[256];
    __shared__ int    amLast;
    __shared__ float  t0[JC * TSTRIDE];  // double-buffered ypred chunks
    __shared__ float  t1[JC * TSTRIDE];

    const int bl  = blockIdx.x;
    const int tid = threadIdx.x;
    const int w   = tid >> 5;
    const int l   = tid & 31;
    const float INF = __int_as_float(0x7f800000);

    const float* yb = ypred + (size_t)bl * (JDIM * NPTS);

    // ---- prefetch ypred chunks 0,1 under phase 1 ----
    prefetch_chunk16(t0, yb, tid);
    prefetch_chunk16(t1, yb + JC * NPTS, tid);

    // ---- load xyz, squared norms (fixed fma order => diag v == -sq exact) ----
    {
        const float* xb = xyz + (size_t)bl * NPTS * 3;
        float x = xb[tid * 3 + 0];
        float y = xb[tid * 3 + 1];
        float z = xb[tid * 3 + 2];
        float sq = fmaf(z, z, fmaf(y, y, x * x));
        float* fA = (float*)pA;
        float* fB = (float*)pB;
        int base = (tid >> 1) * 4 + (tid & 1);
        fA[base + 0] = x;
        fA[base + 2] = y;
        fB[base + 0] = z;
        fB[base + 2] = sq;
    }
    __syncthreads();

    // ---- phase 1: thread (u,h) scans candidate half h for rows u and u+256 ----
    const int u = tid & 255;
    const int h = tid >> 8;                 // warp-uniform
    const int wdiag = u >> 5;               // warp-uniform masked-group window

    const float* fA = (const float*)pA;
    const float* fB = (const float*)pB;
    const ulonglong2* A = (const ulonglong2*)pA;
    const ulonglong2* B = (const ulonglong2*)pB;

    // row 0 = u, row 1 = u + 256 (table base1 = base0 + 512)
    unsigned long long x20, y20, z20, x21, y21, z21;
    float negsq0, negsq1;
    {
        int b0 = (u >> 1) * 4 + (u & 1);
        float x0 = fA[b0], y0 = fA[b0 + 2], z0 = fB[b0], s0 = fB[b0 + 2];
        float x1 = fA[b0 + 512], y1 = fA[b0 + 514], z1 = fB[b0 + 512], s1 = fB[b0 + 514];
        x20 = pack2(x0, x0); y20 = pack2(y0, y0); z20 = pack2(z0, z0); negsq0 = -s0;
        x21 = pack2(x1, x1); y21 = pack2(y1, y1); z21 = pack2(z1, z1); negsq1 = -s1;
    }
    const unsigned long long c2 = pack2(-2.0f, -2.0f);

    float bx0 = -INF, bx1 = -INF, bn0 = INF, bn1 = INF;
    int gx0 = 0, gx1 = 0, gn0 = 0, gn1 = 0;

    #pragma unroll 1
    for (int g = 0; g < 32; ++g) {          // 32 groups x 4 pairs (8 candidates)
        const int pb = (h << 7) + (g << 2);
        float v0[8], v1[8];
        #pragma unroll
        for (int p = 0; p < 4; ++p) {
            ulonglong2 a = A[pb + p];
            ulonglong2 b = B[pb + p];
            float2 r0 = pairv(a, b, x20, y20, z20, c2);
            float2 r1 = pairv(a, b, x21, y21, z21, c2);
            v0[2 * p] = r0.x; v0[2 * p + 1] = r0.y;
            v1[2 * p] = r1.x; v1[2 * p + 1] = r1.y;
        }
        float gm0 = max8(v0);
        if (gm0 > bx0) { bx0 = gm0; gx0 = g; }
        float gm1 = max8(v1);
        if (gm1 > bx1) { bx1 = gm1; gx1 = g; }

        float q0, q1;
        if ((g >> 2) == wdiag) {
            // masked row = u+256h: row0 masked iff h==0, row1 iff h==1
            q0 = h ? min8(v0) : min8m(v0, negsq0, INF);
            q1 = h ? min8m(v1, negsq1, INF) : min8(v1);
        } else {
            q0 = min8(v0);
            q1 = min8(v1);
        }
        if (q0 < bn0) { bn0 = q0; gn0 = g; }
        if (q1 < bn1) { bn1 = q1; gn1 = g; }
    }

    // ---- O(1) exact first-occurrence epilogue on winning groups ----
    int ix0 = rescan_max(A, B, x20, y20, z20, c2, (h << 7) + (gx0 << 2), bx0);
    int ix1 = rescan_max(A, B, x21, y21, z21, c2, (h << 7) + (gx1 << 2), bx1);
    bool m0 = (h == 0) && ((gn0 >> 2) == wdiag);
    bool m1 = (h == 1) && ((gn1 >> 2) == wdiag);
    int in0 = rescan_min(A, B, x20, y20, z20, c2, (h << 7) + (gn0 << 2), bn0, m0, negsq0, INF);
    int in1 = rescan_min(A, B, x21, y21, z21, c2, (h << 7) + (gn1 << 2), bn1, m1, negsq1, INF);

    // ---- merge halves (ties keep half 0 = lower candidate indices) ----
    if (h) {
        mMx[u] = bx0;        miMx[u] = ix0;
        mMn[u] = bn0;        miMn[u] = in0;
        mMx[u + 256] = bx1;  miMx[u + 256] = ix1;
        mMn[u + 256] = bn1;  miMn[u + 256] = in1;
    }
    __syncthreads();
    if (!h) {
        if (mMx[u] > bx0) ix0 = miMx[u];
        if (mMn[u] < bn0) in0 = miMn[u];
        sidx[u] = ix0 | (in0 << 16);
        if (mMx[u + 256] > bx1) ix1 = miMx[u + 256];
        if (mMn[u + 256] < bn1) in1 = miMn[u + 256];
        sidx[u + 256] = ix1 | (in1 << 16);
    }
    __syncthreads();   // sidx published; table readers done

    // ---- phase 2: double-buffered pipeline, lane-half target split ----
    // lane l -> j-row (l&15); targets (w*32 + (l>>4)*16 + i), i in [0,16)
    const int half = l >> 4;
    const int r16 = l & 15;
    const int tb = (w << 5) + (half << 4);
    const int* sw = sidx + tb;

    float acc = 0.0f;
    #pragma unroll 1
    for (int c = 0; c < NCH; ++c) {
        if (c < NCH - 1) { asm volatile("cp.async.wait_group 1;" ::: "memory"); }
        else             { asm volatile("cp.async.wait_group 0;" ::: "memory"); }
        __syncthreads();                       // chunk c visible to all

        const float* tbuf = (c & 1) ? t1 : t0;
        const float* tl = tbuf + r16 * TSTRIDE;
        const float* ta = tl + tb;
        #pragma unroll
        for (int i = 0; i < 16; ++i) {
            int pk = sw[i];                    // 2-addr broadcast LDS
            int mt = pk & 0xffff;
            int nt = ((unsigned)pk) >> 16;
            float a  = ta[i];                  // all 32 banks distinct
            float b  = tl[mt];                 // <=2-way (two 16-bank windows)
            float cc = tl[nt];
            acc = fmaf(a, b - cc, acc);
        }
        __syncthreads();                       // all reads of buffer done
        if (c < NCH - 2) {
            prefetch_chunk16((c & 1) ? t1 : t0,
                             yb + (size_t)(c + 2) * (JC * NPTS), tid);
        }
    }

    // ---- deterministic reduction: warp butterfly + fixed-order sums ----
    double d = (double)acc;
    #pragma unroll
    for (int off = 16; off > 0; off >>= 1)
        d += __shfl_xor_sync(0xffffffffu, d, off);
    if (l == 0) redbuf[w] = d;
    __syncthreads();

    if (tid == 0) {
        double s = 0.0;
        #pragma unroll
        for (int i = 0; i < 16; ++i) s += redbuf[i];
        g_partials[bl] = s;
        __threadfence();
        unsigned t = atomicAdd(&g_ticket, 1u);
        amLast = (t == NBL - 1) ? 1 : 0;
    }
    __syncthreads();

    // ---- fused finalize: last block sums partials in fixed order ----
    if (amLast) {
        if (tid < NBL) redbuf[tid] = ((const volatile double*)g_partials)[tid];
        __syncthreads();
        #pragma unroll
        for (int s2 = NBL / 2; s2 > 0; s2 >>= 1) {
            if (tid < s2) redbuf[tid] += redbuf[tid + s2];
            __syncthreads();
        }
        if (tid == 0) {
            out[0] = (float)(redbuf[0] / (double)((size_t)NBL * NPTS));
            g_ticket = 0;   // reset for next graph replay
        }
    }
}

extern "C" void kernel_launch(void* const* d_in, const int* in_sizes, int n_in,
                              void* d_out, int out_size) {
    const float* ypred = (const float*)d_in[0];
    const float* xyz   = (const float*)d_in[1];
    float* out = (float*)d_out;
    cll_fused_kernel<<<NBL, 512>>>(ypred, xyz, out);
}

// round 10
// speedup vs baseline: 1.0421x; 1.0368x over previous
#include <cuda_runtime.h>

// ypred: [B=8, L=32, J=128, N=512] fp32 -> d_in[0]
// xyz:   [B=8, L=32, N=512, 3]     fp32 -> d_in[1]
// out:   scalar fp32 mean
#define NPTS 512
#define JDIM 128
#define JCHUNK 32            // j-rows per chunk (stored as 16 interleaved pairs)
#define NCHUNK 4
#define T2STRIDE 513         // float2 stride (odd) => conflict-free column reads
#define NBL 256

__device__ double g_partials[NBL];
__device__ unsigned int g_ticket = 0;

// ---- packed f32x2 helpers (sm_100+) ----
__device__ __forceinline__ unsigned long long pack2(float lo, float hi) {
    unsigned long long r;
    asm("mov.b64 %0, {%1, %2};" : "=l"(r) : "f"(lo), "f"(hi));
    return r;
}
__device__ __forceinline__ void unpack2(unsigned long long v, float& lo, float& hi) {
    asm("mov.b64 {%0, %1}, %2;" : "=f"(lo), "=f"(hi) : "l"(v));
}
__device__ __forceinline__ unsigned long long mul2(unsigned long long a, unsigned long long b) {
    unsigned long long d;
    asm("mul.rn.f32x2 %0, %1, %2;" : "=l"(d) : "l"(a), "l"(b));
    return d;
}
__device__ __forceinline__ unsigned long long add2(unsigned long long a, unsigned long long b) {
    unsigned long long d;
    asm("add.rn.f32x2 %0, %1, %2;" : "=l"(d) : "l"(a), "l"(b));
    return d;
}
__device__ __forceinline__ unsigned long long fma2(unsigned long long a, unsigned long long b,
                                                   unsigned long long c) {
    unsigned long long d;
    asm("fma.rn.f32x2 %0, %1, %2, %3;" : "=l"(d) : "l"(a), "l"(b), "l"(c));
    return d;
}

// v-pair for one row against point-pair (a=(x0x1,y0y1), b=(z0z1,sq0sq1))
__device__ __forceinline__ float2 pairv(ulonglong2 a, ulonglong2 b,
                                        unsigned long long x2,
                                        unsigned long long y2,
                                        unsigned long long z2,
                                        unsigned long long c2) {
    unsigned long long dot = mul2(x2, a.x);
    dot = fma2(y2, a.y, dot);
    dot = fma2(z2, b.x, dot);
    unsigned long long val = fma2(dot, c2, b.y);   // v = sq_m - 2*dot
    float2 r;
    unpack2(val, r.x, r.y);
    return r;
}

__device__ __forceinline__ float max8(const float* v) {
    return fmaxf(fmaxf(fmaxf(v[0], v[1]), fmaxf(v[2], v[3])),
                 fmaxf(fmaxf(v[4], v[5]), fmaxf(v[6], v[7])));
}
__device__ __forceinline__ float min8(const float* v) {
    return fminf(fminf(fminf(v[0], v[1]), fminf(v[2], v[3])),
                 fminf(fminf(v[4], v[5]), fminf(v[6], v[7])));
}
__device__ __forceinline__ float min8m(const float* v, float negsq, float INF) {
    float u[8];
    #pragma unroll
    for (int q = 0; q < 8; ++q) u[q] = (v[q] > negsq) ? v[q] : INF;
    return min8(u);
}

__device__ __forceinline__ int rescan_max(const ulonglong2* A, const ulonglong2* B,
                                          unsigned long long x2, unsigned long long y2,
                                          unsigned long long z2, unsigned long long c2,
                                          int pb, float best) {
    int idx = 2 * pb;
    bool found = false;
    #pragma unroll
    for (int p = 0; p < 4; ++p) {
        float2 v = pairv(A[pb + p], B[pb + p], x2, y2, z2, c2);
        if (!found && v.x == best) { idx = 2 * (pb + p);     found = true; }
        if (!found && v.y == best) { idx = 2 * (pb + p) + 1; found = true; }
    }
    return idx;
}
__device__ __forceinline__ int rescan_min(const ulonglong2* A, const ulonglong2* B,
                                          unsigned long long x2, unsigned long long y2,
                                          unsigned long long z2, unsigned long long c2,
                                          int pb, float best, bool masked, float negsq,
                                          float INF) {
    int idx = 2 * pb;
    bool found = false;
    #pragma unroll
    for (int p = 0; p < 4; ++p) {
        float2 v = pairv(A[pb + p], B[pb + p], x2, y2, z2, c2);
        float u0 = (masked && !(v.x > negsq)) ? INF : v.x;
        float u1 = (masked && !(v.y > negsq)) ? INF : v.y;
        if (!found && u0 == best) { idx = 2 * (pb + p);     found = true; }
        if (!found && u1 == best) { idx = 2 * (pb + p) + 1; found = true; }
    }
    return idx;
}

// 32 x 4B cp.async: one 32x512 ypred chunk into float2-interleaved tile:
// tile2[jj&15][n] = ( y[32c+(jj&15)][n], y[32c+(jj&15)+16][n] )
__device__ __forceinline__ void prefetch_chunk_i(float* buf, const float* src, int tid) {
    unsigned db = (unsigned)__cvta_generic_to_shared(buf);
    #pragma unroll
    for (int jj = 0; jj < JCHUNK; ++jj) {
        const float* s = src + jj * NPTS + tid;
        unsigned d = db + (unsigned)((((jj & 15) * (2 * T2STRIDE)) + tid * 2 + (jj >> 4)) * 4);
        asm volatile("cp.async.ca.shared.global [%0], [%1], 4;" :: "r"(d), "l"(s));
    }
    asm volatile("cp.async.commit_group;" ::: "memory");
}

__global__ __launch_bounds__(512, 2)
void cll_fused_kernel(const float* __restrict__ ypred,
                      const float* __restrict__ xyz,
                      float* __restrict__ out) {
    __shared__ float4 pA[NPTS / 2];      // (x0,x1,y0,y1) per point pair
    __shared__ float4 pB[NPTS / 2];      // (z0,z1,sq0,sq1)
    __shared__ int    sidx[NPTS];        // packed (imax | imin<<16) per row
    __shared__ float  mMx[NPTS];         // half-1 publish buffers
    __shared__ int    miMx[NPTS];
    __shared__ float  mMn[NPTS];
    __shared__ int    miMn[NPTS];
    __shared__ double redbuf[256];
    __shared__ int    amLast;
    __shared__ __align__(16) float tile[16 * 2 * T2STRIDE];  // 16 pair-rows x 513 float2
                                                             // align: base must be 8B for LDS.64

    const int bl  = blockIdx.x;
    const int tid = threadIdx.x;
    const int w   = tid >> 5;
    const int l   = tid & 31;
    const float INF = __int_as_float(0x7f800000);

    const float* yb = ypred + (size_t)bl * (JDIM * NPTS);

    // ---- prefetch ypred chunk 0 under phase 1 ----
    prefetch_chunk_i(tile, yb, tid);

    // ---- load xyz, squared norms (fixed fma order => diag v == -sq exact) ----
    {
        const float* xb = xyz + (size_t)bl * NPTS * 3;
        float x = xb[tid * 3 + 0];
        float y = xb[tid * 3 + 1];
        float z = xb[tid * 3 + 2];
        float sq = fmaf(z, z, fmaf(y, y, x * x));
        float* fA = (float*)pA;
        float* fB = (float*)pB;
        int base = (tid >> 1) * 4 + (tid & 1);
        fA[base + 0] = x;
        fA[base + 2] = y;
        fB[base + 0] = z;
        fB[base + 2] = sq;
    }
    __syncthreads();

    // ---- phase 1: thread (u,h) scans candidate half h for rows u and u+256 ----
    const int u = tid & 255;
    const int h = tid >> 8;                 // warp-uniform
    const int wdiag = u >> 5;               // warp-uniform masked-group window

    const float* fA = (const float*)pA;
    const float* fB = (const float*)pB;
    const ulonglong2* A = (const ulonglong2*)pA;
    const ulonglong2* B = (const ulonglong2*)pB;

    // row 0 = u, row 1 = u + 256 (table base1 = base0 + 512)
    unsigned long long x20, y20, z20, x21, y21, z21;
    float negsq0, negsq1;
    {
        int b0 = (u >> 1) * 4 + (u & 1);
        float x0 = fA[b0], y0 = fA[b0 + 2], z0 = fB[b0], s0 = fB[b0 + 2];
        float x1 = fA[b0 + 512], y1 = fA[b0 + 514], z1 = fB[b0 + 512], s1 = fB[b0 + 514];
        x20 = pack2(x0, x0); y20 = pack2(y0, y0); z20 = pack2(z0, z0); negsq0 = -s0;
        x21 = pack2(x1, x1); y21 = pack2(y1, y1); z21 = pack2(z1, z1); negsq1 = -s1;
    }
    const unsigned long long c2 = pack2(-2.0f, -2.0f);

    float bx0 = -INF, bx1 = -INF, bn0 = INF, bn1 = INF;
    int gx0 = 0, gx1 = 0, gn0 = 0, gn1 = 0;

    #pragma unroll 1
    for (int g = 0; g < 32; ++g) {          // 32 groups x 4 pairs (8 candidates)
        const int pb = (h << 7) + (g << 2);
        float v0[8], v1[8];
        #pragma unroll
        for (int p = 0; p < 4; ++p) {
            ulonglong2 a = A[pb + p];
            ulonglong2 b = B[pb + p];
            float2 r0 = pairv(a, b, x20, y20, z20, c2);
            float2 r1 = pairv(a, b, x21, y21, z21, c2);
            v0[2 * p] = r0.x; v0[2 * p + 1] = r0.y;
            v1[2 * p] = r1.x; v1[2 * p + 1] = r1.y;
        }
        float gm0 = max8(v0);
        if (gm0 > bx0) { bx0 = gm0; gx0 = g; }
        float gm1 = max8(v1);
        if (gm1 > bx1) { bx1 = gm1; gx1 = g; }

        float q0, q1;
        if ((g >> 2) == wdiag) {
            // masked row = u+256h: row0 masked iff h==0, row1 iff h==1
            q0 = h ? min8(v0) : min8m(v0, negsq0, INF);
            q1 = h ? min8m(v1, negsq1, INF) : min8(v1);
        } else {
            q0 = min8(v0);
            q1 = min8(v1);
        }
        if (q0 < bn0) { bn0 = q0; gn0 = g; }
        if (q1 < bn1) { bn1 = q1; gn1 = g; }
    }

    // ---- O(1) exact first-occurrence epilogue on winning groups ----
    int ix0 = rescan_max(A, B, x20, y20, z20, c2, (h << 7) + (gx0 << 2), bx0);
    int ix1 = rescan_max(A, B, x21, y21, z21, c2, (h << 7) + (gx1 << 2), bx1);
    bool m0 = (h == 0) && ((gn0 >> 2) == wdiag);
    bool m1 = (h == 1) && ((gn1 >> 2) == wdiag);
    int in0 = rescan_min(A, B, x20, y20, z20, c2, (h << 7) + (gn0 << 2), bn0, m0, negsq0, INF);
    int in1 = rescan_min(A, B, x21, y21, z21, c2, (h << 7) + (gn1 << 2), bn1, m1, negsq1, INF);

    // ---- merge halves (ties keep half 0 = lower candidate indices) ----
    if (h) {
        mMx[u] = bx0;        miMx[u] = ix0;
        mMn[u] = bn0;        miMn[u] = in0;
        mMx[u + 256] = bx1;  miMx[u + 256] = ix1;
        mMn[u + 256] = bn1;  miMn[u + 256] = in1;
    }
    __syncthreads();
    if (!h) {
        if (mMx[u] > bx0) ix0 = miMx[u];
        if (mMn[u] < bn0) in0 = miMn[u];
        sidx[u] = ix0 | (in0 << 16);
        if (mMx[u + 256] > bx1) ix1 = miMx[u + 256];
        if (mMn[u + 256] < bn1) in1 = miMn[u + 256];
        sidx[u + 256] = ix1 | (in1 << 16);
    }

    // ---- phase 2: float2-interleaved, conflict-free LDS.64 gathered dots ----
    // lane l: pair-row r = l&15 (j-rows 32c+r and 32c+r+16); half = l>>4
    // targets: t = 32w + 16*half + i, i in [0,16)
    asm volatile("cp.async.wait_group 0;" ::: "memory");
    __syncthreads();   // chunk 0 ready; sidx published; table readers done

    const int r16  = l & 15;
    const int tbse = (w << 5) + ((l >> 4) << 4);
    const int* sw = sidx + tbse;
    const unsigned long long sgn = 0x8000000080000000ULL;

    unsigned long long acc2 = pack2(0.0f, 0.0f);
    #pragma unroll 1
    for (int c = 0; c < NCHUNK; ++c) {
        const unsigned long long* tl =
            (const unsigned long long*)(tile + r16 * (2 * T2STRIDE));
        #pragma unroll
        for (int i = 0; i < 16; ++i) {
            int pk = sw[i];                  // 2-address broadcast LDS
            int mt = pk & 0xffff;
            int nt = ((unsigned)pk) >> 16;
            unsigned long long a2 = tl[tbse + i];   // conflict-free LDS.64
            unsigned long long b2 = tl[mt];          // conflict-free (uniform col)
            unsigned long long d2 = tl[nt];          // conflict-free
            acc2 = fma2(a2, add2(b2, d2 ^ sgn), acc2);   // acc += a*(b-c), x2
        }
        if (c + 1 < NCHUNK) {
            __syncthreads();     // everyone done reading chunk c
            prefetch_chunk_i(tile, yb + (size_t)(c + 1) * (JCHUNK * NPTS), tid);
            asm volatile("cp.async.wait_group 0;" ::: "memory");
            __syncthreads();     // chunk c+1 visible
        }
    }
    float accx, accy;
    unpack2(acc2, accx, accy);

    // ---- deterministic reduction: warp butterfly + fixed-order sums ----
    double d = (double)accx + (double)accy;
    #pragma unroll
    for (int off = 16; off > 0; off >>= 1)
        d += __shfl_xor_sync(0xffffffffu, d, off);
    if (l == 0) redbuf[w] = d;
    __syncthreads();

    if (tid == 0) {
        double s = 0.0;
        #pragma unroll
        for (int i = 0; i < 16; ++i) s += redbuf[i];
        g_partials[bl] = s;
        __threadfence();
        unsigned t = atomicAdd(&g_ticket, 1u);
        amLast = (t == NBL - 1) ? 1 : 0;
    }
    __syncthreads();

    // ---- fused finalize: last block sums partials in fixed order ----
    if (amLast) {
        if (tid < NBL) redbuf[tid] = ((const volatile double*)g_partials)[tid];
        __syncthreads();
        #pragma unroll
        for (int s2 = NBL / 2; s2 > 0; s2 >>= 1) {
            if (tid < s2) redbuf[tid] += redbuf[tid + s2];
            __syncthreads();
        }
        if (tid == 0) {
            out[0] = (float)(redbuf[0] / (double)((size_t)NBL * NPTS));
            g_ticket = 0;   // reset for next graph replay
        }
    }
}

extern "C" void kernel_launch(void* const* d_in, const int* in_sizes, int n_in,
                              void* d_out, int out_size) {
    const float* ypred = (const float*)d_in[0];
    const float* xyz   = (const float*)d_in[1];
    float* out = (float*)d_out;
    cll_fused_kernel<<<NBL, 512>>>(ypred, xyz, out);
}

// round 11
// speedup vs baseline: 1.0484x; 1.0061x over previous
#include <cuda_runtime.h>

// ypred: [B=8, L=32, J=128, N=512] fp32 -> d_in[0]
// xyz:   [B=8, L=32, N=512, 3]     fp32 -> d_in[1]
// out:   scalar fp32 mean
#define NPTS 512
#define JDIM 128
#define JCHUNK 32
#define NCHUNK 4
#define TSTRIDE 513          // odd stride => conflict-free column reads
#define NBL 256

__device__ double g_partials[NBL];
__device__ unsigned int g_ticket = 0;

// ---- packed f32x2 helpers (sm_100+) ----
__device__ __forceinline__ unsigned long long pack2(float lo, float hi) {
    unsigned long long r;
    asm("mov.b64 %0, {%1, %2};" : "=l"(r) : "f"(lo), "f"(hi));
    return r;
}
__device__ __forceinline__ void unpack2(unsigned long long v, float& lo, float& hi) {
    asm("mov.b64 {%0, %1}, %2;" : "=f"(lo), "=f"(hi) : "l"(v));
}
__device__ __forceinline__ unsigned long long mul2(unsigned long long a, unsigned long long b) {
    unsigned long long d;
    asm("mul.rn.f32x2 %0, %1, %2;" : "=l"(d) : "l"(a), "l"(b));
    return d;
}
__device__ __forceinline__ unsigned long long fma2(unsigned long long a, unsigned long long b,
                                                   unsigned long long c) {
    unsigned long long d;
    asm("fma.rn.f32x2 %0, %1, %2, %3;" : "=l"(d) : "l"(a), "l"(b), "l"(c));
    return d;
}

// v-pair for one row against point-pair (a=(x0x1,y0y1), b=(z0z1,sq0sq1))
__device__ __forceinline__ float2 pairv(ulonglong2 a, ulonglong2 b,
                                        unsigned long long x2,
                                        unsigned long long y2,
                                        unsigned long long z2,
                                        unsigned long long c2) {
    unsigned long long dot = mul2(x2, a.x);
    dot = fma2(y2, a.y, dot);
    dot = fma2(z2, b.x, dot);
    unsigned long long val = fma2(dot, c2, b.y);   // v = sq_m - 2*dot
    float2 r;
    unpack2(val, r.x, r.y);
    return r;
}

__device__ __forceinline__ float max8(const float* v) {
    return fmaxf(fmaxf(fmaxf(v[0], v[1]), fmaxf(v[2], v[3])),
                 fmaxf(fmaxf(v[4], v[5]), fmaxf(v[6], v[7])));
}
__device__ __forceinline__ float min8(const float* v) {
    return fminf(fminf(fminf(v[0], v[1]), fminf(v[2], v[3])),
                 fminf(fminf(v[4], v[5]), fminf(v[6], v[7])));
}
__device__ __forceinline__ float min8m(const float* v, float negsq, float INF) {
    float u[8];
    #pragma unroll
    for (int q = 0; q < 8; ++q) u[q] = (v[q] > negsq) ? v[q] : INF;
    return min8(u);
}

__device__ __forceinline__ int rescan_max(const ulonglong2* A, const ulonglong2* B,
                                          unsigned long long x2, unsigned long long y2,
                                          unsigned long long z2, unsigned long long c2,
                                          int pb, float best) {
    int idx = 2 * pb;
    bool found = false;
    #pragma unroll
    for (int p = 0; p < 4; ++p) {
        float2 v = pairv(A[pb + p], B[pb + p], x2, y2, z2, c2);
        if (!found && v.x == best) { idx = 2 * (pb + p);     found = true; }
        if (!found && v.y == best) { idx = 2 * (pb + p) + 1; found = true; }
    }
    return idx;
}
__device__ __forceinline__ int rescan_min(const ulonglong2* A, const ulonglong2* B,
                                          unsigned long long x2, unsigned long long y2,
                                          unsigned long long z2, unsigned long long c2,
                                          int pb, float best, bool masked, float negsq,
                                          float INF) {
    int idx = 2 * pb;
    bool found = false;
    #pragma unroll
    for (int p = 0; p < 4; ++p) {
        float2 v = pairv(A[pb + p], B[pb + p], x2, y2, z2, c2);
        float u0 = (masked && !(v.x > negsq)) ? INF : v.x;
        float u1 = (masked && !(v.y > negsq)) ? INF : v.y;
        if (!found && u0 == best) { idx = 2 * (pb + p);     found = true; }
        if (!found && u1 == best) { idx = 2 * (pb + p) + 1; found = true; }
    }
    return idx;
}

// one tournament group (4 pairs = 8 candidates) for both rows; updates the
// caller's accumulator set (independent even/odd sets give 2x chain ILP)
__device__ __forceinline__ void proc_group(
    const ulonglong2* __restrict__ A, const ulonglong2* __restrict__ B,
    int g, int pbase, int wdiag, int h,
    unsigned long long x20, unsigned long long y20, unsigned long long z20,
    unsigned long long x21, unsigned long long y21, unsigned long long z21,
    unsigned long long c2, float negsq0, float negsq1, float INF,
    float& bx0, int& gx0, float& bn0, int& gn0,
    float& bx1, int& gx1, float& bn1, int& gn1) {
    const int pb = pbase + (g << 2);
    float v0[8], v1[8];
    #pragma unroll
    for (int p = 0; p < 4; ++p) {
        ulonglong2 a = A[pb + p];
        ulonglong2 b = B[pb + p];
        float2 r0 = pairv(a, b, x20, y20, z20, c2);
        float2 r1 = pairv(a, b, x21, y21, z21, c2);
        v0[2 * p] = r0.x; v0[2 * p + 1] = r0.y;
        v1[2 * p] = r1.x; v1[2 * p + 1] = r1.y;
    }
    float gm0 = max8(v0);
    if (gm0 > bx0) { bx0 = gm0; gx0 = g; }
    float gm1 = max8(v1);
    if (gm1 > bx1) { bx1 = gm1; gx1 = g; }

    float q0, q1;
    if ((g >> 2) == wdiag) {
        q0 = h ? min8(v0) : min8m(v0, negsq0, INF);
        q1 = h ? min8m(v1, negsq1, INF) : min8(v1);
    } else {
        q0 = min8(v0);
        q1 = min8(v1);
    }
    if (q0 < bn0) { bn0 = q0; gn0 = g; }
    if (q1 < bn1) { bn1 = q1; gn1 = g; }
}

// 32 x 4B cp.async: one 32x512 ypred chunk into the stride-513 tile
__device__ __forceinline__ void prefetch_chunk(float* buf, const float* src, int tid) {
    unsigned db = (unsigned)__cvta_generic_to_shared(buf);
    #pragma unroll
    for (int r = 0; r < JCHUNK; ++r) {
        const float* s = src + r * NPTS + tid;
        unsigned d = db + (unsigned)((r * TSTRIDE + tid) * 4);
        asm volatile("cp.async.ca.shared.global [%0], [%1], 4;" :: "r"(d), "l"(s));
    }
    asm volatile("cp.async.commit_group;" ::: "memory");
}

__global__ __launch_bounds__(512, 2)
void cll_fused_kernel(const float* __restrict__ ypred,
                      const float* __restrict__ xyz,
                      float* __restrict__ out) {
    __shared__ float4 pA[NPTS / 2];      // (x0,x1,y0,y1) per point pair
    __shared__ float4 pB[NPTS / 2];      // (z0,z1,sq0,sq1)
    __shared__ int    sidx[NPTS];        // packed (imax | imin<<16) per row
    __shared__ float  mMx[NPTS];         // half-1 publish buffers
    __shared__ int    miMx[NPTS];
    __shared__ float  mMn[NPTS];
    __shared__ int    miMn[NPTS];
    __shared__ double redbuf[256];
    __shared__ int    amLast;
    __shared__ float  tile[JCHUNK * TSTRIDE];

    const int bl  = blockIdx.x;
    const int tid = threadIdx.x;
    const int w   = tid >> 5;
    const int l   = tid & 31;
    const float INF = __int_as_float(0x7f800000);

    const float* yb = ypred + (size_t)bl * (JDIM * NPTS);

    // ---- prefetch ypred chunk 0 under phase 1 ----
    prefetch_chunk(tile, yb, tid);

    // ---- load xyz, squared norms (fixed fma order => diag v == -sq exact) ----
    {
        const float* xb = xyz + (size_t)bl * NPTS * 3;
        float x = xb[tid * 3 + 0];
        float y = xb[tid * 3 + 1];
        float z = xb[tid * 3 + 2];
        float sq = fmaf(z, z, fmaf(y, y, x * x));
        float* fA = (float*)pA;
        float* fB = (float*)pB;
        int base = (tid >> 1) * 4 + (tid & 1);
        fA[base + 0] = x;
        fA[base + 2] = y;
        fB[base + 0] = z;
        fB[base + 2] = sq;
    }
    __syncthreads();

    // ---- phase 1: thread (u,h) scans candidate half h for rows u and u+256 ----
    const int u = tid & 255;
    const int h = tid >> 8;                 // warp-uniform
    const int wdiag = u >> 5;               // warp-uniform masked-group window

    const float* fA = (const float*)pA;
    const float* fB = (const float*)pB;
    const ulonglong2* A = (const ulonglong2*)pA;
    const ulonglong2* B = (const ulonglong2*)pB;

    unsigned long long x20, y20, z20, x21, y21, z21;
    float negsq0, negsq1;
    {
        int b0 = (u >> 1) * 4 + (u & 1);
        float x0 = fA[b0], y0 = fA[b0 + 2], z0 = fB[b0], s0 = fB[b0 + 2];
        float x1 = fA[b0 + 512], y1 = fA[b0 + 514], z1 = fB[b0 + 512], s1 = fB[b0 + 514];
        x20 = pack2(x0, x0); y20 = pack2(y0, y0); z20 = pack2(z0, z0); negsq0 = -s0;
        x21 = pack2(x1, x1); y21 = pack2(y1, y1); z21 = pack2(z1, z1); negsq1 = -s1;
    }
    const unsigned long long c2 = pack2(-2.0f, -2.0f);
    const int pbase = h << 7;

    // even/odd group accumulator sets: two independent dependency chains
    float bx0e = -INF, bx1e = -INF, bn0e = INF, bn1e = INF;
    float bx0o = -INF, bx1o = -INF, bn0o = INF, bn1o = INF;
    int gx0e = 0, gx1e = 0, gn0e = 0, gn1e = 0;
    int gx0o = 1, gx1o = 1, gn0o = 1, gn1o = 1;

    #pragma unroll 1
    for (int g = 0; g < 32; g += 2) {
        proc_group(A, B, g,     pbase, wdiag, h, x20, y20, z20, x21, y21, z21,
                   c2, negsq0, negsq1, INF,
                   bx0e, gx0e, bn0e, gn0e, bx1e, gx1e, bn1e, gn1e);
        proc_group(A, B, g + 1, pbase, wdiag, h, x20, y20, z20, x21, y21, z21,
                   c2, negsq0, negsq1, INF,
                   bx0o, gx0o, bn0o, gn0o, bx1o, gx1o, bn1o, gn1o);
    }

    // ---- exact merge of even/odd chains: (value, group) lexicographic ----
    float bx0, bx1, bn0, bn1;
    int gx0, gx1, gn0, gn1;
    if (bx0o > bx0e || (bx0o == bx0e && gx0o < gx0e)) { bx0 = bx0o; gx0 = gx0o; }
    else                                              { bx0 = bx0e; gx0 = gx0e; }
    if (bx1o > bx1e || (bx1o == bx1e && gx1o < gx1e)) { bx1 = bx1o; gx1 = gx1o; }
    else                                              { bx1 = bx1e; gx1 = gx1e; }
    if (bn0o < bn0e || (bn0o == bn0e && gn0o < gn0e)) { bn0 = bn0o; gn0 = gn0o; }
    else                                              { bn0 = bn0e; gn0 = gn0e; }
    if (bn1o < bn1e || (bn1o == bn1e && gn1o < gn1e)) { bn1 = bn1o; gn1 = gn1o; }
    else                                              { bn1 = bn1e; gn1 = gn1e; }

    // ---- O(1) exact first-occurrence epilogue on winning groups ----
    int ix0 = rescan_max(A, B, x20, y20, z20, c2, pbase + (gx0 << 2), bx0);
    int ix1 = rescan_max(A, B, x21, y21, z21, c2, pbase + (gx1 << 2), bx1);
    bool m0 = (h == 0) && ((gn0 >> 2) == wdiag);
    bool m1 = (h == 1) && ((gn1 >> 2) == wdiag);
    int in0 = rescan_min(A, B, x20, y20, z20, c2, pbase + (gn0 << 2), bn0, m0, negsq0, INF);
    int in1 = rescan_min(A, B, x21, y21, z21, c2, pbase + (gn1 << 2), bn1, m1, negsq1, INF);

    // ---- merge halves (ties keep half 0 = lower candidate indices) ----
    if (h) {
        mMx[u] = bx0;        miMx[u] = ix0;
        mMn[u] = bn0;        miMn[u] = in0;
        mMx[u + 256] = bx1;  miMx[u + 256] = ix1;
        mMn[u + 256] = bn1;  miMn[u + 256] = in1;
    }
    __syncthreads();
    if (!h) {
        if (mMx[u] > bx0) ix0 = miMx[u];
        if (mMn[u] < bn0) in0 = miMn[u];
        sidx[u] = ix0 | (in0 << 16);
        if (mMx[u + 256] > bx1) ix1 = miMx[u + 256];
        if (mMn[u + 256] < bn1) in1 = miMn[u + 256];
        sidx[u + 256] = ix1 | (in1 << 16);
    }

    // ---- phase 2: conflict-free gathered dots (indices via LDS broadcast) ----
    asm volatile("cp.async.wait_group 0;" ::: "memory");
    __syncthreads();   // chunk 0 ready; sidx published; table readers done

    float acc = 0.0f;
    const float* tl = tile + l * TSTRIDE;    // lane l owns j-row l
    const float* ta = tl + (w << 5);         // this warp's target columns
    const int* sw = sidx + (w << 5);

    #pragma unroll 1
    for (int c = 0; c < NCHUNK; ++c) {
        #pragma unroll
        for (int i = 0; i < 32; ++i) {
            int pk = sw[i];                  // broadcast LDS (warp-uniform)
            int mt = pk & 0xffff;
            int nt = ((unsigned)pk) >> 16;
            float a  = ta[i];    // bank (l+32w+i)%32 : conflict-free
            float b  = tl[mt];   // bank (l+mt)%32    : conflict-free
            float cc = tl[nt];   // bank (l+nt)%32    : conflict-free
            acc = fmaf(a, b - cc, acc);
        }
        if (c + 1 < NCHUNK) {
            __syncthreads();     // everyone done reading chunk c
            prefetch_chunk(tile, yb + (size_t)(c + 1) * (JCHUNK * NPTS), tid);
            asm volatile("cp.async.wait_group 0;" ::: "memory");
            __syncthreads();     // chunk c+1 visible
        }
    }

    // ---- deterministic reduction: warp butterfly + fixed-order sums ----
    double d = (double)acc;
    #pragma unroll
    for (int off = 16; off > 0; off >>= 1)
        d += __shfl_xor_sync(0xffffffffu, d, off);
    if (l == 0) redbuf[w] = d;
    __syncthreads();

    if (tid == 0) {
        double s = 0.0;
        #pragma unroll
        for (int i = 0; i < 16; ++i) s += redbuf[i];
        g_partials[bl] = s;
        __threadfence();
        unsigned t = atomicAdd(&g_ticket, 1u);
        amLast = (t == NBL - 1) ? 1 : 0;
    }
    __syncthreads();

    // ---- fused finalize: last block sums partials in fixed order ----
    if (amLast) {
        if (tid < NBL) redbuf[tid] = ((const volatile double*)g_partials)[tid];
        __syncthreads();
        #pragma unroll
        for (int s2 = NBL / 2; s2 > 0; s2 >>= 1) {
            if (tid < s2) redbuf[tid] += redbuf[tid + s2];
            __syncthreads();
        }
        if (tid == 0) {
            out[0] = (float)(redbuf[0] / (double)((size_t)NBL * NPTS));
            g_ticket = 0;   // reset for next graph replay
        }
    }
}

extern "C" void kernel_launch(void* const* d_in, const int* in_sizes, int n_in,
                              void* d_out, int out_size) {
    const float* ypred = (const float*)d_in[0];
    const float* xyz   = (const float*)d_in[1];
    float* out = (float*)d_out;
    cll_fused_kernel<<<NBL, 512>>>(ypred, xyz, out);
}